// round 2
// baseline (speedup 1.0000x reference)
#include <cuda_runtime.h>
#include <math.h>

#define BB 32
#define SS 32
#define TT 31
#define HH 256
#define H3 768
#define VV 12000
#define NTOK 32
#define BOUND 16

// ---------------- metadata (written by control kernel) ----------------
__device__ signed char g_la[TT][BB];
__device__ signed char g_npop[TT][BB];
__device__ signed char g_pop_slot[TT][BB][SS];
__device__ signed char g_pop_tok[TT][BB][SS];
__device__ signed char g_spush_slot[TT][BB];   // -1 none
__device__ signed char g_spush_tok[TT][BB];    // -1 = rfinal value, >=0 token
__device__ signed char g_bpush_tok[TT][BB];    // -1 none
__device__ signed char g_stop[TT][BB];         // stack top after step

// precomputed token xw tables: set 0=a,1=b,2=s,3=r
__device__ __align__(16) float g_tokxw[4][NTOK][H3];
// attention outputs, row = b*TT + t
__device__ __align__(16) float g_att[BB * TT][HH];

// ---------------- control kernel: pure integer RNNG simulation ----------------
__global__ void control_kernel(const int* __restrict__ actions) {
    int b = threadIdx.x;
    int st = -1, tt_ = -1, bt = 0, acc = 1;  // bt=0 after initial buffer push
    signed char tm[SS];
    signed char stok[SS];

    for (int t = 0; t < TT; t++) {
        int a = actions[b * SS + t];
        int la = a * acc;
        int is_red = (la == 2) ? 1 : 0;
        int is_nt  = (la > 2 && la < BOUND) ? 1 : 0;
        int is_gen = (la >= BOUND) ? 1 : 0;

        // ---- reduce pops ----
        int np = 0;
        int ir = is_red, aok = 1;
        for (int i = 0; i < SS; i++) {
            if (!(ir && aok)) break;
            int can1 = (st >= 0);
            int pslot = -1;
            if (can1) { pslot = st; st--; }
            aok = aok & can1;
            int tag = 0;
            if (ir && aok) {
                int can2 = (tt_ >= 0);
                if (can2) { tag = tm[tt_]; tt_--; }
                aok = aok & can2;
            }
            int outm = ir & aok;
            if (outm) {
                g_pop_slot[t][b][np] = (signed char)pslot;
                g_pop_tok[t][b][np]  = stok[pslot];
                np++;
            }
            ir = (ir - tag) * aok;
        }
        int racc = aok;
        int sslot = -1, stokv = -2;
        // reduce pushes
        if (is_red && racc) {
            int can = (st + 1 < SS);
            if (can) { st++; sslot = st; stokv = -1; stok[st] = -1; }
            racc &= can;
            if (racc) {
                int can2 = (tt_ + 1 < SS);
                if (can2) { tt_++; tm[tt_] = 0; }
                racc &= can2;
            }
        }
        // global red_mult (cross-batch coupling)
        unsigned ball = __ballot_sync(0xffffffffu, is_red);
        int tot = np;
        for (int o = 16; o > 0; o >>= 1) tot += __shfl_xor_sync(0xffffffffu, tot, o);
        int red_mult = 1;
        if (ball) red_mult = (tot == 0) ? 0 : racc;
        acc *= red_mult;

        // ---- NT push (uses pre-reduce flags, per reference ordering) ----
        if (is_nt) {
            int s5 = (st + 1 < SS);
            if (s5) { st++; stok[st] = (signed char)la; sslot = st; stokv = la; }
            acc *= s5;
            if (s5) {
                int s6 = (tt_ + 1 < SS);
                if (s6) { tt_++; tm[tt_] = 1; }
                acc *= s6;
            }
        }
        // ---- GEN push ----
        int bpush = -1;
        if (is_gen) {
            int s7 = (st + 1 < SS);
            if (s7) { st++; stok[st] = (signed char)la; sslot = st; stokv = la; }
            acc *= s7;
            int s8 = 1;
            if (s7) {
                s8 = (tt_ + 1 < SS);
                if (s8) { tt_++; tm[tt_] = 0; }
                acc *= s8;
            }
            if (s7 && s8) {
                int s9 = (bt + 1 < SS);
                if (s9) { bt++; bpush = la; }
                acc *= s9;
            }
        }
        g_bpush_tok[t][b]  = (signed char)bpush;
        g_la[t][b]         = (signed char)la;
        g_npop[t][b]       = (signed char)np;
        g_spush_slot[t][b] = (signed char)sslot;
        g_spush_tok[t][b]  = (signed char)stokv;
        g_stop[t][b]       = (signed char)st;
    }
}

// ---------------- token xw tables ----------------
__global__ void tokxw_kernel(const float* __restrict__ embed,
                             const float* __restrict__ aW, const float* __restrict__ ab,
                             const float* __restrict__ bW, const float* __restrict__ bb,
                             const float* __restrict__ sW, const float* __restrict__ sb,
                             const float* __restrict__ rW, const float* __restrict__ rb) {
    int tok = blockIdx.x;
    int set = blockIdx.y;
    const float* W  = (set == 0) ? aW : (set == 1) ? bW : (set == 2) ? sW : rW;
    const float* bi = (set == 0) ? ab : (set == 1) ? bb : (set == 2) ? sb : rb;
    int tid = threadIdx.x;  // 192 threads, 4 cols each
    const float4* W4 = (const float4*)W;
    float4 acc = __ldg((const float4*)bi + tid);
    const float* x = embed + (size_t)tok * HH;
#pragma unroll 8
    for (int k = 0; k < HH; k++) {
        float xk = __ldg(x + k);
        float4 w = __ldg(W4 + k * 192 + tid);
        acc.x += xk * w.x; acc.y += xk * w.y; acc.z += xk * w.z; acc.w += xk * w.w;
    }
    ((float4*)(&g_tokxw[set][tok][0]))[tid] = acc;
}

// ---------------- device helpers ----------------
// out[768] = x[256] @ M[256x768] (+ optional bias). 192 active threads, float4 cols.
__device__ __forceinline__ void mv768(const float* __restrict__ M, const float* __restrict__ x,
                                      float* out, const float* __restrict__ bias, int tid) {
    if (tid < 192) {
        const float4* M4 = (const float4*)M;
        float4 acc;
        if (bias) acc = __ldg((const float4*)bias + tid);
        else      acc = make_float4(0.f, 0.f, 0.f, 0.f);
#pragma unroll 8
        for (int k = 0; k < HH; k++) {
            float xk = x[k];
            float4 m = __ldg(M4 + k * 192 + tid);
            acc.x += xk * m.x; acc.y += xk * m.y; acc.z += xk * m.z; acc.w += xk * m.w;
        }
        ((float4*)out)[tid] = acc;
    }
    __syncthreads();
}

// GRU gate combine: h' = (1-z)h + z n ; hu/hprev may be null (zero hidden state)
__device__ __forceinline__ void gru_fin(const float* __restrict__ xw, const float* __restrict__ hu,
                                        const float* __restrict__ hprev, float* hout, int tid) {
    float xz = xw[tid], xr = xw[HH + tid], xn = xw[2 * HH + tid];
    float hz = 0.f, hr = 0.f, hn = 0.f, hp = 0.f;
    if (hu) { hz = hu[tid]; hr = hu[HH + tid]; hn = hu[2 * HH + tid]; }
    if (hprev) hp = hprev[tid];
    float z = 1.f / (1.f + expf(-(xz + hz)));
    float r = 1.f / (1.f + expf(-(xr + hr)));
    float n = tanhf(xn + r * hn);
    hout[tid] = (1.f - z) * hp + z * n;
    __syncthreads();
}

// ---------------- main sequential kernel: one CTA per batch element ----------------
extern __shared__ float smem_f[];
__global__ __launch_bounds__(256) void main_kernel(
    const float* __restrict__ aU, const float* __restrict__ bU,
    const float* __restrict__ sU, const float* __restrict__ rU,
    const float* __restrict__ sW, const float* __restrict__ sb,
    const float* __restrict__ rW, const float* __restrict__ rb,
    const float* __restrict__ Wc, const float* __restrict__ bc) {
    int b = blockIdx.x, tid = threadIdx.x;

    float* sm_v = smem_f;           // [32][256] stack values (only rfinal slots read)
    float* hs   = sm_v + SS * HH;   // [32][256] hidden-state stack
    float* bufh = hs + SS * HH;     // [256]
    float* ah   = bufh + HH;        // [256]
    float* hred = ah + HH;          // [256]
    float* s_hu = hred + HH;        // [768]
    float* s_xw = s_hu + H3;        // [768]
    float* s_cat = s_xw + H3;       // [768]
    float* s_pt  = s_cat + H3;      // [4*256]

    // initial buffer push: bufh = GRU_b(embed[START=1], 0)  (hu=0 -> no U read)
    gru_fin(&g_tokxw[1][1][0], nullptr, nullptr, bufh, tid);
    bool ah_init = false;

    for (int t = 0; t < TT; t++) {
        int la = g_la[t][b];
        int np = g_npop[t][b];

        // ---- reduce GRU over popped values ----
        for (int i = 0; i < np; i++) {
            int slot = g_pop_slot[t][b][i];
            int tok  = g_pop_tok[t][b][i];
            const float* xw;
            if (tok >= 0) {
                xw = &g_tokxw[3][tok][0];
            } else {
                mv768(rW, &sm_v[slot * HH], s_xw, rb, tid);
                xw = s_xw;
            }
            const float* hp = (i == 0) ? nullptr : hred;
            if (hp) mv768(rU, hp, s_hu, nullptr, tid);
            gru_fin(xw, hp ? s_hu : nullptr, hp, hred, tid);
        }

        // ---- stack push (reduce result / NT / GEN) ----
        int ss = g_spush_slot[t][b];
        if (ss >= 0) {
            int stokv = g_spush_tok[t][b];
            const float* xw;
            if (stokv >= 0) {
                xw = &g_tokxw[2][stokv][0];
            } else {
                sm_v[ss * HH + tid] = hred[tid];
                __syncthreads();
                mv768(sW, hred, s_xw, sb, tid);
                xw = s_xw;
            }
            const float* hp = (ss > 0) ? &hs[(ss - 1) * HH] : nullptr;
            if (hp) mv768(sU, hp, s_hu, nullptr, tid);
            gru_fin(xw, hp ? s_hu : nullptr, hp, &hs[ss * HH], tid);
        }

        // ---- buffer push (GEN) ----
        int btok = g_bpush_tok[t][b];
        if (btok >= 0) {
            mv768(bU, bufh, s_hu, nullptr, tid);
            gru_fin(&g_tokxw[1][btok][0], s_hu, bufh, bufh, tid);
        }

        // ---- action GRU (always) ----
        {
            const float* hp = ah_init ? ah : nullptr;
            if (hp) mv768(aU, hp, s_hu, nullptr, tid);
            gru_fin(&g_tokxw[0][la][0], hp ? s_hu : nullptr, hp, ah, tid);
            ah_init = true;
        }

        // ---- attention: att = tanh([stk_e, ah, buf_e] @ Wc + bc) ----
        int stop = g_stop[t][b];
        s_cat[tid]          = (stop >= 0) ? hs[stop * HH + tid] : 0.f;
        s_cat[HH + tid]     = ah[tid];
        s_cat[2 * HH + tid] = bufh[tid];
        __syncthreads();
        {
            int p  = tid >> 6;   // k-part 0..3 (192 k each)
            int cg = tid & 63;   // col group (4 cols)
            const float4* Wc4 = (const float4*)Wc;  // row stride = 64 float4
            float4 acc = make_float4(0.f, 0.f, 0.f, 0.f);
            int k0 = p * 192;
#pragma unroll 8
            for (int k = 0; k < 192; k++) {
                float xk = s_cat[k0 + k];
                float4 w = __ldg(Wc4 + (size_t)(k0 + k) * 64 + cg);
                acc.x += xk * w.x; acc.y += xk * w.y; acc.z += xk * w.z; acc.w += xk * w.w;
            }
            ((float4*)s_pt)[p * 64 + cg] = acc;
            __syncthreads();
            float v = s_pt[tid] + s_pt[256 + tid] + s_pt[512 + tid] + s_pt[768 + tid] + __ldg(bc + tid);
            g_att[b * TT + t][tid] = tanhf(v);
            __syncthreads();
        }
    }
}

// ---------------- logits GEMM: [992,256] @ [256,12000] + bp ----------------
#define GBM 32
#define GBN 128
#define GKC 32
__global__ __launch_bounds__(256) void gemm_kernel(const float* __restrict__ Wp,
                                                   const float* __restrict__ bp,
                                                   float* __restrict__ out) {
    __shared__ float As[GBM * HH];    // 32 KB
    __shared__ float Bs[GKC * GBN];   // 16 KB
    int tid = threadIdx.x;
    int c0 = blockIdx.x * GBN;
    int row0 = blockIdx.y * GBM;
    const float* A = (const float*)g_att;

    for (int idx = tid; idx < GBM * HH; idx += 256)
        As[idx] = A[(size_t)row0 * HH + idx];

    float acc[4][4];
#pragma unroll
    for (int i = 0; i < 4; i++)
#pragma unroll
        for (int j = 0; j < 4; j++) acc[i][j] = 0.f;

    int rg = (tid >> 5) << 2;   // row offset 0..28
    int cg = (tid & 31) << 2;   // col offset 0..124

    for (int kk = 0; kk < HH; kk += GKC) {
        for (int idx = tid; idx < GKC * GBN; idx += 256) {
            int k = idx >> 7, c = idx & 127;
            int gc = c0 + c;
            Bs[idx] = (gc < VV) ? __ldg(&Wp[(size_t)(kk + k) * VV + gc]) : 0.f;
        }
        __syncthreads();
#pragma unroll
        for (int k = 0; k < GKC; k++) {
            float a0 = As[(rg + 0) * HH + kk + k];
            float a1 = As[(rg + 1) * HH + kk + k];
            float a2 = As[(rg + 2) * HH + kk + k];
            float a3 = As[(rg + 3) * HH + kk + k];
            float4 b4 = ((const float4*)(Bs + k * GBN))[cg >> 2];
            acc[0][0] += a0 * b4.x; acc[0][1] += a0 * b4.y; acc[0][2] += a0 * b4.z; acc[0][3] += a0 * b4.w;
            acc[1][0] += a1 * b4.x; acc[1][1] += a1 * b4.y; acc[1][2] += a1 * b4.z; acc[1][3] += a1 * b4.w;
            acc[2][0] += a2 * b4.x; acc[2][1] += a2 * b4.y; acc[2][2] += a2 * b4.z; acc[2][3] += a2 * b4.w;
            acc[3][0] += a3 * b4.x; acc[3][1] += a3 * b4.y; acc[3][2] += a3 * b4.z; acc[3][3] += a3 * b4.w;
        }
        __syncthreads();
    }
#pragma unroll
    for (int i = 0; i < 4; i++) {
#pragma unroll
        for (int j = 0; j < 4; j++) {
            int gc = c0 + cg + j;
            if (gc < VV)
                out[(size_t)(row0 + rg + i) * VV + gc] = acc[i][j] + __ldg(bp + gc);
        }
    }
}

// ---------------- argmax per row ----------------
__global__ void argmax_kernel(const float* __restrict__ logits, float* __restrict__ preds) {
    int row = blockIdx.x;
    int tid = threadIdx.x;
    const float* p = logits + (size_t)row * VV;
    float best = -3.4e38f;
    int bi = VV;
    for (int c = tid; c < VV; c += 256) {
        float v = p[c];
        if (v > best) { best = v; bi = c; }
    }
    __shared__ float sv[256];
    __shared__ int si[256];
    sv[tid] = best; si[tid] = bi;
    __syncthreads();
    for (int o = 128; o > 0; o >>= 1) {
        if (tid < o) {
            if (sv[tid + o] > sv[tid] || (sv[tid + o] == sv[tid] && si[tid + o] < si[tid])) {
                sv[tid] = sv[tid + o]; si[tid] = si[tid + o];
            }
        }
        __syncthreads();
    }
    if (tid == 0) preds[row] = (float)si[0];
}

// ---------------- launch ----------------
extern "C" void kernel_launch(void* const* d_in, const int* in_sizes, int n_in,
                              void* d_out, int out_size) {
    const int*   actions = (const int*)d_in[0];
    const float* embed = (const float*)d_in[1];
    const float* aW = (const float*)d_in[2];
    const float* aU = (const float*)d_in[3];
    const float* ab = (const float*)d_in[4];
    const float* bW = (const float*)d_in[5];
    const float* bU = (const float*)d_in[6];
    const float* bb = (const float*)d_in[7];
    const float* sW = (const float*)d_in[8];
    const float* sU = (const float*)d_in[9];
    const float* sb = (const float*)d_in[10];
    const float* rW = (const float*)d_in[11];
    const float* rU = (const float*)d_in[12];
    const float* rb = (const float*)d_in[13];
    const float* Wc = (const float*)d_in[14];
    const float* bc = (const float*)d_in[15];
    const float* Wp = (const float*)d_in[16];
    const float* bp = (const float*)d_in[17];

    float* outf = (float*)d_out;
    size_t nl = (size_t)BB * TT * VV;
    float* preds = nullptr;
    float* logits;
    if ((size_t)out_size >= nl + (size_t)BB * TT) {
        preds = outf;
        logits = outf + BB * TT;
    } else {
        logits = outf;
    }

    control_kernel<<<1, 32>>>(actions);
    tokxw_kernel<<<dim3(NTOK, 4), 192>>>(embed, aW, ab, bW, bb, sW, sb, rW, rb);

    size_t shbytes = (size_t)(SS * HH * 2 + HH * 3 + H3 * 3 + 4 * HH) * sizeof(float);
    cudaFuncSetAttribute(main_kernel, cudaFuncAttributeMaxDynamicSharedMemorySize, (int)shbytes);
    main_kernel<<<BB, 256, shbytes>>>(aU, bU, sU, rU, sW, sb, rW, rb, Wc, bc);

    dim3 gg((VV + GBN - 1) / GBN, (BB * TT) / GBM);
    gemm_kernel<<<gg, 256>>>(Wp, bp, logits);
    if (preds) argmax_kernel<<<BB * TT, 256>>>(logits, preds);
}